// round 6
// baseline (speedup 1.0000x reference)
#include <cuda_runtime.h>
#include <cuda_bf16.h>
#include <cstdint>

// ---------------------------------------------------------------------------
// Problem: B=16, DIM=96, H=W=64.  Output (16,96,64,64) = out[b][c][w][h].
// ---------------------------------------------------------------------------
#define NB   16
#define NC   96
#define NHW  4096
#define BN_RS 0.9999950000374994f   // 1/sqrt(1+1e-5)

// scratch (device globals — allocation-free)
__device__ float g_x2[NB * NC * NHW];     // pos-conv + residual, NCHW  (25 MB)
__device__ float g_u [NB * 384 * NHW];    // ffn pin output, [b][o][h][w] (100 MB)

// ---------------------------------------------------------------------------
// helpers
// ---------------------------------------------------------------------------
__device__ __forceinline__ unsigned long long pack2(float lo, float hi) {
    unsigned long long r;
    asm("mov.b64 %0, {%1, %2};" : "=l"(r) : "f"(lo), "f"(hi));
    return r;
}
__device__ __forceinline__ void unpack2(unsigned long long v, float& lo, float& hi) {
    asm("mov.b64 {%0, %1}, %2;" : "=f"(lo), "=f"(hi) : "l"(v));
}
// packed fp32x2 FMA (SASS FFMA2): 2x scalar FFMA throughput on sm_103a
__device__ __forceinline__ unsigned long long fma2(unsigned long long a,
                                                   unsigned long long b,
                                                   unsigned long long c) {
    unsigned long long d;
    asm("fma.rn.f32x2 %0, %1, %2, %3;" : "=l"(d) : "l"(a), "l"(b), "l"(c));
    return d;
}

// exact-erf GELU via Abramowitz-Stegun 7.1.26 (|erf err| <= 1.5e-7)
__device__ __forceinline__ float gelu_f(float x) {
    float u = 0.7071067811865476f * x;
    float a = fabsf(u);
    float t = __fdividef(1.0f, fmaf(0.3275911f, a, 1.0f));
    float p = t * fmaf(t, fmaf(t, fmaf(t, fmaf(t, 1.061405429f, -1.453152027f),
                                        1.421413741f), -0.284496736f), 0.254829592f);
    float e = __expf(-u * u);
    float erfa = fmaf(-p, e, 1.0f);
    erfa = copysignf(erfa, u);
    return 0.5f * x * (1.0f + erfa);
}

// ---------------------------------------------------------------------------
// Kernel 1: g_x2 = x + dwconv3x3(x, pos_w) + pos_b      (NCHW)
// ---------------------------------------------------------------------------
__global__ __launch_bounds__(256) void k1_pos(const float* __restrict__ x,
                                              const float* __restrict__ pw,
                                              const float* __restrict__ pb) {
    int idx = blockIdx.x * 256 + threadIdx.x;
    int w  = idx & 63;
    int h  = (idx >> 6) & 63;
    int bc = idx >> 12;
    int c  = bc % NC;
    const float* base = x + ((size_t)bc << 12);
    float s = __ldg(pb + c);
    const float* wp = pw + c * 9;
#pragma unroll
    for (int a = 0; a < 3; a++) {
        int hh = h + a - 1;
        if ((unsigned)hh < 64u) {
#pragma unroll
            for (int bb = 0; bb < 3; bb++) {
                int ww = w + bb - 1;
                if ((unsigned)ww < 64u)
                    s = fmaf(__ldg(wp + a * 3 + bb), base[hh * 64 + ww], s);
            }
        }
    }
    g_x2[idx] = x[idx] + s;
}

// ---------------------------------------------------------------------------
// shared GEMM micro-kernel: E[64px][96d] += A[96k][64px] * W[96k][97pad d]
// thread (tx,ty): px = ty*8..+7 (as 4 packed pairs), d = tx*3..+2
// A reads are warp-broadcast; W reads stride-3 over 32 lanes (conflict-free).
// ---------------------------------------------------------------------------
__device__ __forceinline__ void gemm96(const float* sA, const float* sW,
                                       int tx, int ty, unsigned long long* acc) {
    const int d0 = tx * 3;
    const float* aB = sA + ty * 8;
#pragma unroll 4
    for (int y = 0; y < 96; y++) {
        const unsigned long long* ap = (const unsigned long long*)(aB + y * 64);
        unsigned long long A0 = ap[0], A1 = ap[1], A2 = ap[2], A3 = ap[3];
        const float* wp = sW + y * 97 + d0;
        float w0 = wp[0], w1 = wp[1], w2v = wp[2];
        unsigned long long W0 = pack2(w0, w0);
        unsigned long long W1 = pack2(w1, w1);
        unsigned long long W2 = pack2(w2v, w2v);
        acc[0]  = fma2(A0, W0, acc[0]);  acc[1]  = fma2(A0, W1, acc[1]);  acc[2]  = fma2(A0, W2, acc[2]);
        acc[3]  = fma2(A1, W0, acc[3]);  acc[4]  = fma2(A1, W1, acc[4]);  acc[5]  = fma2(A1, W2, acc[5]);
        acc[6]  = fma2(A2, W0, acc[6]);  acc[7]  = fma2(A2, W1, acc[7]);  acc[8]  = fma2(A2, W2, acc[8]);
        acc[9]  = fma2(A3, W0, acc[9]);  acc[10] = fma2(A3, W1, acc[10]); acc[11] = fma2(A3, W2, acc[11]);
    }
}

// on-the-fly A-chunk generation: A[y][px] = gelu(s0*conv_k(z[px], y) + bias0)
template <int K>
__device__ __forceinline__ void agen(float* sA, const float* zrow,
                                     int apx, int ay0,
                                     const float* wt, float s0, float bias0) {
    float wl[K];
#pragma unroll
    for (int i = 0; i < K; i++) wl[i] = __ldg(wt + i);
#pragma unroll
    for (int r = 0; r < 24; r++) {
        int y = ay0 + r * 4;
        float s = 0.f;
#pragma unroll
        for (int tp = 0; tp < K; tp++) {
            int yy = y + tp - (K / 2);
            if ((unsigned)yy < 96u) s = fmaf(wl[tp], zrow[yy], s);
        }
        sA[y * 64 + apx] = gelu_f(fmaf(s0, s, bias0));
    }
}

// ---------------------------------------------------------------------------
// Kernel 2: per-(b,h)-row fused pipeline
//   LN3 residual -> LN1 -> patch-embed (convs+gelu+big GEMM+bn2 gelu)
//   -> +y +z residual -> LN2 -> pin matmul (96->384) -> g_u
// ---------------------------------------------------------------------------
struct P2 {
    const float *ln1g, *ln1b, *ln2g, *ln2b, *ln3g, *ln3b;
    const float *w3a, *b3a, *bga, *bba;
    const float *w3b, *b3b, *bgb, *bbb;
    const float *w3c, *b3c, *bgc, *bbc;
    const float *w2, *b2, *bn2g, *bn2b;
    const float *pinw, *pinb;
};

#define OFF_Y 0            // [64px][97] y = v + LN3(v)
#define OFF_Z 6208         // [64px][97] z = LN1(y); later y2
#define OFF_A 12416        // [96][64]  A chunk [k][px]; later ynorm^T [c][px]
#define OFF_W 18560        // [96][97]  w2 / pinw chunk [k][d]
#define SMEM2_FLOATS 27872
#define SMEM2_BYTES (SMEM2_FLOATS * 4)

__global__ __launch_bounds__(256, 2) void k2_main(P2 p) {
    extern __shared__ float sm[];
    const int t  = threadIdx.x;
    const int b  = blockIdx.x >> 6;
    const int h  = blockIdx.x & 63;
    const int tx = t & 31, ty = t >> 5;
    const int apx = t & 63, ay0 = t >> 6;
    // staging index decomposition for element t of a 96x96 chunk (dd = w2 row)
    const int dd0 = t / 96, yy0 = t - dd0 * 96;

    // ---- load x2 row (NCHW gather, coalesced) into y[w][c] ----
    const float* xrow = g_x2 + (size_t)b * NC * NHW + h * 64;
#pragma unroll
    for (int i = 0; i < 24; i++) {
        int e = t + i * 256;
        int c = e >> 6, w = e & 63;
        sm[OFF_Y + w * 97 + c] = xrow[(size_t)c * NHW + w];
    }
    __syncthreads();

    // ---- per-pixel: y = v + LN3(v);  z = LN1(y) ----
    if (t < 64) {
        float* vy = sm + OFF_Y + t * 97;
        float s0 = 0.f, s1 = 0.f;
        for (int c = 0; c < 96; c += 2) { s0 += vy[c]; s1 += vy[c + 1]; }
        float m = (s0 + s1) * (1.f / 96.f);
        s0 = 0.f; s1 = 0.f;
        for (int c = 0; c < 96; c += 2) {
            float d0 = vy[c] - m, d1 = vy[c + 1] - m;
            s0 = fmaf(d0, d0, s0); s1 = fmaf(d1, d1, s1);
        }
        float inv = rsqrtf((s0 + s1) * (1.f / 96.f) + 1e-6f);
        s0 = 0.f; s1 = 0.f;
        for (int c = 0; c < 96; c++) {
            float v = vy[c];
            float yv = v + (v - m) * inv * __ldg(p.ln3g + c) + __ldg(p.ln3b + c);
            vy[c] = yv;
            ((c & 1) ? s1 : s0) += yv;
        }
        float m1 = (s0 + s1) * (1.f / 96.f);
        s0 = 0.f; s1 = 0.f;
        for (int c = 0; c < 96; c += 2) {
            float d0 = vy[c] - m1, d1 = vy[c + 1] - m1;
            s0 = fmaf(d0, d0, s0); s1 = fmaf(d1, d1, s1);
        }
        float inv1 = rsqrtf((s0 + s1) * (1.f / 96.f) + 1e-6f);
        float* vz = sm + OFF_Z + t * 97;
        for (int c = 0; c < 96; c++)
            vz[c] = (vy[c] - m1) * inv1 * __ldg(p.ln1g + c) + __ldg(p.ln1b + c);
    }

    // ---- big GEMM over 24 o-chunks: e[px][d] = sum_{o,y} A(px,o,y)*w2[d][o][y]
    unsigned long long acc[12];
#pragma unroll
    for (int i = 0; i < 12; i++) acc[i] = 0ull;

    float* sA = sm + OFF_A;
    float* sW = sm + OFF_W;
    const float* zrow = sm + OFF_Z + apx * 97;

    for (int o = 0; o < 24; o++) {
        // -- prefetch w2 chunk into registers (latency hidden behind agen) --
        float wbuf[36];
        {
            const float* wg = p.w2 + o * 96;
            int d_ = dd0, y_ = yy0;
#pragma unroll
            for (int i = 0; i < 36; i++) {
                wbuf[i] = __ldg(wg + d_ * 2304 + y_);
                y_ += 64; d_ += 2;
                if (y_ >= 96) { y_ -= 96; d_ += 1; }
            }
        }
        __syncthreads();   // previous chunk fully consumed (sA/sW reusable)
        int br = o >> 3, j = o & 7;
        if (br == 0) {
            float s0 = __ldg(p.bga + j) * BN_RS;
            float bi = fmaf(s0, __ldg(p.b3a + j), __ldg(p.bba + j));
            agen<3>(sA, zrow, apx, ay0, p.w3a + j * 3, s0, bi);
        } else if (br == 1) {
            float s0 = __ldg(p.bgb + j) * BN_RS;
            float bi = fmaf(s0, __ldg(p.b3b + j), __ldg(p.bbb + j));
            agen<5>(sA, zrow, apx, ay0, p.w3b + j * 5, s0, bi);
        } else {
            float s0 = __ldg(p.bgc + j) * BN_RS;
            float bi = fmaf(s0, __ldg(p.b3c + j), __ldg(p.bbc + j));
            agen<7>(sA, zrow, apx, ay0, p.w3c + j * 7, s0, bi);
        }
        // -- commit prefetched w2 chunk: sW[y][d] = w2[d*2304 + o*96 + y] --
        {
            int d_ = dd0, y_ = yy0;
#pragma unroll
            for (int i = 0; i < 36; i++) {
                sW[y_ * 97 + d_] = wbuf[i];
                y_ += 64; d_ += 2;
                if (y_ >= 96) { y_ -= 96; d_ += 1; }
            }
        }
        __syncthreads();
        gemm96(sA, sW, tx, ty, acc);
    }

    // ---- epilogue: y2 = y + z + gelu(bn2(e + b2))  (store into z region) ----
    {
        const float* yr = sm + OFF_Y;
        float* zr = sm + OFF_Z;
        int d0 = tx * 3;
#pragma unroll
        for (int j = 0; j < 3; j++) {
            int d = d0 + j;
            float s  = __ldg(p.bn2g + d) * BN_RS;
            float bb = __ldg(p.bn2b + d);
            float b2v = __ldg(p.b2 + d);
#pragma unroll
            for (int pp = 0; pp < 4; pp++) {
                int px = ty * 8 + 2 * pp;
                float lo, hi; unpack2(acc[pp * 3 + j], lo, hi);
                float v0 = gelu_f(fmaf(s, lo + b2v, bb));
                float v1 = gelu_f(fmaf(s, hi + b2v, bb));
                zr[px * 97 + d]       = yr[px * 97 + d]       + zr[px * 97 + d]       + v0;
                zr[(px + 1) * 97 + d] = yr[(px + 1) * 97 + d] + zr[(px + 1) * 97 + d] + v1;
            }
        }
    }
    __syncthreads();

    // ---- LN2 + transpose into sA: sA[c][px] = ynorm ----
    if (t < 64) {
        const float* v = sm + OFF_Z + t * 97;
        float s0 = 0.f, s1 = 0.f;
        for (int c = 0; c < 96; c += 2) { s0 += v[c]; s1 += v[c + 1]; }
        float m = (s0 + s1) * (1.f / 96.f);
        s0 = 0.f; s1 = 0.f;
        for (int c = 0; c < 96; c += 2) {
            float d0 = v[c] - m, d1 = v[c + 1] - m;
            s0 = fmaf(d0, d0, s0); s1 = fmaf(d1, d1, s1);
        }
        float inv = rsqrtf((s0 + s1) * (1.f / 96.f) + 1e-6f);
        for (int c = 0; c < 96; c++)
            sA[c * 64 + t] = (v[c] - m) * inv * __ldg(p.ln2g + c) + __ldg(p.ln2b + c);
    }

    // ---- pin matmul: u[px][o] = sum_c ynorm[px][c]*pin_w[o][c] + pin_b ----
    for (int oc = 0; oc < 4; oc++) {
        __syncthreads();  // sW reuse safe; first iter also publishes sA
        const float* wg = p.pinw + (oc * 96) * 96;
        for (int i = t; i < 9216; i += 256) {
            int oo = i / 96;
            int cc = i - oo * 96;
            sW[cc * 97 + oo] = __ldg(wg + oo * 96 + cc);
        }
        __syncthreads();
#pragma unroll
        for (int i = 0; i < 12; i++) acc[i] = 0ull;
        gemm96(sA, sW, tx, ty, acc);

        float* ub = g_u + (((size_t)b * 384 + oc * 96) * 64 + h) * 64;
#pragma unroll
        for (int j = 0; j < 3; j++) {
            int o_ = tx * 3 + j;
            float bv = __ldg(p.pinb + oc * 96 + o_);
            float* dst = ub + (size_t)o_ * NHW + ty * 8;
#pragma unroll
            for (int pp = 0; pp < 4; pp++) {
                float lo, hi; unpack2(acc[pp * 3 + j], lo, hi);
                float2 st; st.x = lo + bv; st.y = hi + bv;
                *(float2*)(dst + 2 * pp) = st;
            }
        }
    }
}

// ---------------------------------------------------------------------------
// Kernel 3: FFN tail. g_u[b][o][h][w] -> dwconv (index-swapped) -> gate ->
//           pout (192->96) -> out[b][d][w][h] = 2*f
// block = (b, 8x8 spatial tile), 256 threads, 4 channels per iteration.
// ---------------------------------------------------------------------------
struct P3 { const float *dww, *dwb, *poutw, *poutb; float* out; };

#define K3_KV   0                     // 384*9 transposed dw kernels
#define K3_DWB  3456                  // 384
#define K3_POB  3840                  // 96
#define K3_PW   3936                  // [192c][97d] pout_w  (also reused as sOut)
#define K3_HALO 22560                 // 8 tiles * 100
#define K3_G    23360                 // 4 ch * 64
#define SMEM3_FLOATS 23616
#define SMEM3_BYTES (SMEM3_FLOATS * 4)

__global__ __launch_bounds__(256, 2) void k3_ffn(P3 p) {
    extern __shared__ float sm[];
    const int t = threadIdx.x;
    const int b = blockIdx.x >> 6;
    const int tile = blockIdx.x & 63;
    const int h0 = (tile >> 3) * 8, w0 = (tile & 7) * 8;
    const int tx = t & 31, ty = t >> 5;

    // stage dw kernels transposed: skv[o*9 + j*3 + i] = dw_w[o*9 + i*3 + j]
    for (int i = t; i < 3456; i += 256) {
        int o = i / 9;
        int rr = i - o * 9;
        int jj = rr / 3, ii = rr - jj * 3;
        sm[K3_KV + i] = __ldg(p.dww + o * 9 + ii * 3 + jj);
    }
    for (int i = t; i < 384; i += 256) sm[K3_DWB + i] = __ldg(p.dwb + i);
    if (t < 96) sm[K3_POB + t] = __ldg(p.poutb + t);
    // stage pout_w: sPW[c*97 + d] = pout_w[d*192 + c]
    for (int i = t; i < 18432; i += 256) {
        int d = i / 192;
        int c = i - d * 192;
        sm[K3_PW + c * 97 + d] = __ldg(p.poutw + i);
    }
    __syncthreads();

    const float* ub = g_u + (size_t)b * 384 * NHW;
    unsigned long long acc[12];
#pragma unroll
    for (int i = 0; i < 12; i++) acc[i] = 0ull;

    // conv assignment: all 256 threads busy (4 channels x 64 px)
    const int cch = t >> 6;           // 0..3
    const int cpx = t & 63;
    const int chl = cpx >> 3, cwl = cpx & 7;

    for (int c = 0; c < 192; c += 4) {
        __syncthreads();   // prev iter's conv done with halo; rank-1 done with g
        // halo: 8 tiles of 10x10 (tl 0..3 = u1 ch c..c+3, tl 4..7 = u2)
        for (int e = t; e < 800; e += 256) {
            int tl = e / 100;
            int pos = e - tl * 100;
            int r = pos / 10, cc = pos - r * 10;
            int hh = h0 + r - 1, ww = w0 + cc - 1;
            int ch = c + (tl & 3) + ((tl & 4) ? 192 : 0);
            float v = 0.f;
            if ((unsigned)hh < 64u && (unsigned)ww < 64u)
                v = ub[(size_t)ch * NHW + hh * 64 + ww];
            sm[K3_HALO + tl * 100 + pos] = v;
        }
        __syncthreads();
        // conv + gate: thread -> (channel cch, pixel cpx)
        {
            const float* ha = sm + K3_HALO + cch * 100;
            const float* hb = sm + K3_HALO + (cch + 4) * 100;
            const float* kva = sm + K3_KV + (c + cch) * 9;
            const float* kvb = sm + K3_KV + (c + cch + 192) * 9;
            float d1 = sm[K3_DWB + c + cch];
            float d2 = sm[K3_DWB + c + cch + 192];
#pragma unroll
            for (int j = 0; j < 3; j++)
#pragma unroll
                for (int i2 = 0; i2 < 3; i2++) {
                    float t1 = ha[(chl + j) * 10 + cwl + i2];
                    float t2 = hb[(chl + j) * 10 + cwl + i2];
                    d1 = fmaf(kva[j * 3 + i2], t1, d1);
                    d2 = fmaf(kvb[j * 3 + i2], t2, d2);
                }
            sm[K3_G + cch * 64 + cpx] = gelu_f(d1) * d2;
        }
        __syncthreads();
        // rank-1 updates: acc[px][d] += g[px] * pout_w[d][c+cc2]
#pragma unroll
        for (int cc2 = 0; cc2 < 4; cc2++) {
            const unsigned long long* gp =
                (const unsigned long long*)(sm + K3_G + cc2 * 64 + ty * 8);
            unsigned long long G0 = gp[0], G1 = gp[1], G2 = gp[2], G3 = gp[3];
            const float* wr = sm + K3_PW + (c + cc2) * 97 + tx * 3;
            float w0v = wr[0], w1v = wr[1], w2v = wr[2];
            unsigned long long W0 = pack2(w0v, w0v);
            unsigned long long W1 = pack2(w1v, w1v);
            unsigned long long W2 = pack2(w2v, w2v);
            acc[0]  = fma2(G0, W0, acc[0]);  acc[1]  = fma2(G0, W1, acc[1]);  acc[2]  = fma2(G0, W2, acc[2]);
            acc[3]  = fma2(G1, W0, acc[3]);  acc[4]  = fma2(G1, W1, acc[4]);  acc[5]  = fma2(G1, W2, acc[5]);
            acc[6]  = fma2(G2, W0, acc[6]);  acc[7]  = fma2(G2, W1, acc[7]);  acc[8]  = fma2(G2, W2, acc[8]);
            acc[9]  = fma2(G3, W0, acc[9]);  acc[10] = fma2(G3, W1, acc[10]); acc[11] = fma2(G3, W2, acc[11]);
        }
    }
    __syncthreads();

    // stage result transposed in smem: sOut[d*66 + wl*8 + hl] = 2*(acc + pout_b)
    float* so = sm + K3_PW;   // reuse
#pragma unroll
    for (int j = 0; j < 3; j++) {
        int d = tx * 3 + j;
        float bv = sm[K3_POB + d];
#pragma unroll
        for (int pp = 0; pp < 4; pp++) {
            float lo, hi; unpack2(acc[pp * 3 + j], lo, hi);
            so[d * 66 + (2 * pp) * 8 + ty]     = 2.f * (lo + bv);
            so[d * 66 + (2 * pp + 1) * 8 + ty] = 2.f * (hi + bv);
        }
    }
    __syncthreads();

    // out[b][d][w0+wl][h0 + 0..7] : 32B contiguous runs
    for (int e = t; e < 768; e += 256) {
        int d = e >> 3, wl = e & 7;
        const float2* s2 = (const float2*)(so + d * 66 + wl * 8);
        float2 v0 = s2[0], v1 = s2[1], v2 = s2[2], v3 = s2[3];
        float2* dst = (float2*)(p.out + (((size_t)b * 96 + d) * 64 + (w0 + wl)) * 64 + h0);
        dst[0] = v0; dst[1] = v1; dst[2] = v2; dst[3] = v3;
    }
}

// ---------------------------------------------------------------------------
// launch
// ---------------------------------------------------------------------------
extern "C" void kernel_launch(void* const* d_in, const int* in_sizes, int n_in,
                              void* d_out, int out_size) {
    (void)in_sizes; (void)n_in; (void)out_size;
    cudaFuncSetAttribute(k2_main, cudaFuncAttributeMaxDynamicSharedMemorySize, SMEM2_BYTES);
    cudaFuncSetAttribute(k3_ffn,  cudaFuncAttributeMaxDynamicSharedMemorySize, SMEM3_BYTES);

    const float* x    = (const float*)d_in[0];
    const float* posw = (const float*)d_in[1];
    const float* posb = (const float*)d_in[2];

    k1_pos<<<NB * NC * NHW / 256, 256>>>(x, posw, posb);

    P2 p2;
    p2.ln1g = (const float*)d_in[3];  p2.ln1b = (const float*)d_in[4];
    p2.ln2g = (const float*)d_in[5];  p2.ln2b = (const float*)d_in[6];
    p2.ln3g = (const float*)d_in[7];  p2.ln3b = (const float*)d_in[8];
    p2.w3a  = (const float*)d_in[9];  p2.b3a  = (const float*)d_in[10];
    p2.bga  = (const float*)d_in[11]; p2.bba  = (const float*)d_in[12];
    p2.w3b  = (const float*)d_in[13]; p2.b3b  = (const float*)d_in[14];
    p2.bgb  = (const float*)d_in[15]; p2.bbb  = (const float*)d_in[16];
    p2.w3c  = (const float*)d_in[17]; p2.b3c  = (const float*)d_in[18];
    p2.bgc  = (const float*)d_in[19]; p2.bbc  = (const float*)d_in[20];
    p2.w2   = (const float*)d_in[21]; p2.b2   = (const float*)d_in[22];
    p2.bn2g = (const float*)d_in[23]; p2.bn2b = (const float*)d_in[24];
    p2.pinw = (const float*)d_in[25]; p2.pinb = (const float*)d_in[26];
    k2_main<<<NB * 64, 256, SMEM2_BYTES>>>(p2);

    P3 p3;
    p3.dww   = (const float*)d_in[27]; p3.dwb   = (const float*)d_in[28];
    p3.poutw = (const float*)d_in[29]; p3.poutb = (const float*)d_in[30];
    p3.out   = (float*)d_out;
    k3_ffn<<<NB * 64, 256, SMEM3_BYTES>>>(p3);
}

// round 13
// speedup vs baseline: 1.8799x; 1.8799x over previous
#include <cuda_runtime.h>
#include <cuda_bf16.h>
#include <cstdint>

// ---------------------------------------------------------------------------
// Problem: B=16, DIM=96, H=W=64.  Output (16,96,64,64) = out[b][c][w][h].
// ---------------------------------------------------------------------------
#define NB   16
#define NC   96
#define NHW  4096
#define BN_RS 0.9999950000374994f   // 1/sqrt(1+1e-5)

// scratch (device globals — allocation-free)
__device__ float g_x2[NB * NC * NHW];       // pos-conv + residual, NCHW (25 MB)
__device__ float g_y [NB * 64 * 6144];      // y rows [b][h][px][c]      (25 MB)
__device__ float g_u [NB * 384 * NHW];      // ffn pin out [b][o][h][w]  (100 MB)

// ---------------------------------------------------------------------------
// helpers
// ---------------------------------------------------------------------------
__device__ __forceinline__ unsigned long long pack2(float lo, float hi) {
    unsigned long long r;
    asm("mov.b64 %0, {%1, %2};" : "=l"(r) : "f"(lo), "f"(hi));
    return r;
}
__device__ __forceinline__ void unpack2(unsigned long long v, float& lo, float& hi) {
    asm("mov.b64 {%0, %1}, %2;" : "=f"(lo), "=f"(hi) : "l"(v));
}
__device__ __forceinline__ unsigned long long fma2(unsigned long long a,
                                                   unsigned long long b,
                                                   unsigned long long c) {
    unsigned long long d;
    asm("fma.rn.f32x2 %0, %1, %2, %3;" : "=l"(d) : "l"(a), "l"(b), "l"(c));
    return d;
}

// exact-erf GELU via Abramowitz-Stegun 7.1.26 (|erf err| <= 1.5e-7)
__device__ __forceinline__ float gelu_f(float x) {
    float u = 0.7071067811865476f * x;
    float a = fabsf(u);
    float t = __fdividef(1.0f, fmaf(0.3275911f, a, 1.0f));
    float p = t * fmaf(t, fmaf(t, fmaf(t, fmaf(t, 1.061405429f, -1.453152027f),
                                        1.421413741f), -0.284496736f), 0.254829592f);
    float e = __expf(-u * u);
    float erfa = fmaf(-p, e, 1.0f);
    erfa = copysignf(erfa, u);
    return 0.5f * x * (1.0f + erfa);
}

__device__ __forceinline__ uint32_t smem_u32(const void* p) {
    return (uint32_t)__cvta_generic_to_shared(p);
}

#define LDSM4(r0, r1, r2, r3, addr) \
    asm volatile("ldmatrix.sync.aligned.m8n8.x4.shared.b16 {%0,%1,%2,%3}, [%4];" \
                 : "=r"(r0), "=r"(r1), "=r"(r2), "=r"(r3) : "r"(addr))

#define MMA_BF16(d, a, b0_, b1_) \
    asm volatile("mma.sync.aligned.m16n8k16.row.col.f32.bf16.bf16.f32 " \
                 "{%0,%1,%2,%3}, {%4,%5,%6,%7}, {%8,%9}, {%0,%1,%2,%3};" \
                 : "+f"(d[0]), "+f"(d[1]), "+f"(d[2]), "+f"(d[3]) \
                 : "r"(a[0]), "r"(a[1]), "r"(a[2]), "r"(a[3]), "r"(b0_), "r"(b1_))

// ---------------------------------------------------------------------------
// Kernel 1: g_x2 = x + dwconv3x3(x, pos_w) + pos_b      (NCHW)
// ---------------------------------------------------------------------------
__global__ __launch_bounds__(256) void k1_pos(const float* __restrict__ x,
                                              const float* __restrict__ pw,
                                              const float* __restrict__ pb) {
    int idx = blockIdx.x * 256 + threadIdx.x;
    int w  = idx & 63;
    int h  = (idx >> 6) & 63;
    int bc = idx >> 12;
    int c  = bc % NC;
    const float* base = x + ((size_t)bc << 12);
    float s = __ldg(pb + c);
    const float* wp = pw + c * 9;
#pragma unroll
    for (int a = 0; a < 3; a++) {
        int hh = h + a - 1;
        if ((unsigned)hh < 64u) {
#pragma unroll
            for (int bb = 0; bb < 3; bb++) {
                int ww = w + bb - 1;
                if ((unsigned)ww < 64u)
                    s = fmaf(__ldg(wp + a * 3 + bb), base[hh * 64 + ww], s);
            }
        }
    }
    g_x2[idx] = x[idx] + s;
}

// ---------------------------------------------------------------------------
// Kernel 2 — tensor-core version.
// smem byte layout (per block, 91392 B):
//   Z  [64][97] f32 : 24832   (x2 row -> y -> z -> y2 -> u bounce)
//   AH [64][104] bf16: 13312  (A hi)  } reused as Yr [64][97] f32 at epilogue,
//   AL [64][104] bf16: 13312  (A lo)  } then as ynorm hi/lo for pin
//   WH [96][104] bf16: 19968  (W hi)
//   WL [96][104] bf16: 19968  (W lo)
// ---------------------------------------------------------------------------
#define SM_Z   0
#define SM_AH  24832
#define SM_AL  38144
#define SM_WH  51456
#define SM_WL  71424
#define SMEM2_BYTES 91392
#define ASTRIDE 104   // bf16 elements per row (208 B; 8-row ldmatrix phase hits all 32 banks)

struct P2 {
    const float *ln1g, *ln1b, *ln2g, *ln2b, *ln3g, *ln3b;
    const float *w3a, *b3a, *bga, *bba;
    const float *w3b, *b3b, *bgb, *bbb;
    const float *w3c, *b3c, *bgc, *bbc;
    const float *w2, *b2, *bn2g, *bn2b;
    const float *pinw, *pinb;
};

// warp GEMM: D[6][4] += A[64x96 split] * W^T (96x96 split), 3-term hi/lo
__device__ __forceinline__ void mma96(uint32_t aH, uint32_t aL,
                                      uint32_t wH, uint32_t wL,
                                      int mt, int nb, int lane, float D[6][4]) {
    const uint32_t aOff = (uint32_t)((mt * 16 + (lane & 15)) * 208 + ((lane >> 4) << 4));
    const uint32_t bOff = (uint32_t)((nb + ((lane >> 4) << 3) + (lane & 7)) * 208 +
                                     (((lane >> 3) & 1) << 4));
#pragma unroll
    for (int kt = 0; kt < 6; kt++) {
        uint32_t ah[4], al[4];
        LDSM4(ah[0], ah[1], ah[2], ah[3], aH + aOff + kt * 32);
        LDSM4(al[0], al[1], al[2], al[3], aL + aOff + kt * 32);
#pragma unroll
        for (int np = 0; np < 3; np++) {
            uint32_t bh[4], bl[4];
            LDSM4(bh[0], bh[1], bh[2], bh[3], wH + bOff + np * 16 * 208 + kt * 32);
            LDSM4(bl[0], bl[1], bl[2], bl[3], wL + bOff + np * 16 * 208 + kt * 32);
            MMA_BF16(D[2 * np],     ah, bh[0], bh[1]);
            MMA_BF16(D[2 * np],     ah, bl[0], bl[1]);
            MMA_BF16(D[2 * np],     al, bh[0], bh[1]);
            MMA_BF16(D[2 * np + 1], ah, bh[2], bh[3]);
            MMA_BF16(D[2 * np + 1], ah, bl[2], bl[3]);
            MMA_BF16(D[2 * np + 1], al, bh[2], bh[3]);
        }
    }
}

// on-the-fly A-chunk: A[px][y] = gelu(s0*conv_k(z[px],y)+bias0), split to bf16 hi/lo
template <int K>
__device__ __forceinline__ void agen(__nv_bfloat16* aH, __nv_bfloat16* aL,
                                     const float* zrow, int apx, int ay0,
                                     const float* wt, float s0, float bias0) {
    float wl[K];
#pragma unroll
    for (int i = 0; i < K; i++) wl[i] = __ldg(wt + i);
#pragma unroll
    for (int r = 0; r < 24; r++) {
        int y = ay0 + r * 4;
        float s = 0.f;
#pragma unroll
        for (int tp = 0; tp < K; tp++) {
            int yy = y + tp - (K / 2);
            if ((unsigned)yy < 96u) s = fmaf(wl[tp], zrow[yy], s);
        }
        float a = gelu_f(fmaf(s0, s, bias0));
        __nv_bfloat16 hv = __float2bfloat16(a);
        aH[apx * ASTRIDE + y] = hv;
        aL[apx * ASTRIDE + y] = __float2bfloat16(a - __bfloat162float(hv));
    }
}

__global__ __launch_bounds__(256, 2) void k2_main(P2 p) {
    extern __shared__ char smc[];
    float* Zf = (float*)(smc + SM_Z);
    __nv_bfloat16* AH = (__nv_bfloat16*)(smc + SM_AH);
    __nv_bfloat16* AL = (__nv_bfloat16*)(smc + SM_AL);
    __nv_bfloat16* WH = (__nv_bfloat16*)(smc + SM_WH);
    __nv_bfloat16* WL = (__nv_bfloat16*)(smc + SM_WL);
    const uint32_t uAH = smem_u32(AH), uAL = smem_u32(AL);
    const uint32_t uWH = smem_u32(WH), uWL = smem_u32(WL);

    const int t = threadIdx.x;
    const int b = blockIdx.x >> 6;
    const int h = blockIdx.x & 63;
    const int lane = t & 31, warp = t >> 5;
    const int mt = warp & 3, nbw = (warp >> 2) * 48;
    const int apx = t & 63, ay0 = t >> 6;
    const int dd0 = t / 96, yy0 = t - dd0 * 96;   // chunk staging walk start

    // ---- 1. load x2 row (NCHW gather) into Zf[w][c] ----
    const float* xrow = g_x2 + (size_t)b * NC * NHW + h * 64;
#pragma unroll
    for (int i = 0; i < 24; i++) {
        int e = t + i * 256;
        int c = e >> 6, w = e & 63;
        Zf[w * 97 + c] = xrow[(size_t)c * NHW + w];
    }
    __syncthreads();

    // ---- 2. LN3 residual in place: v -> y ----
    if (t < 64) {
        float* vy = Zf + t * 97;
        float s0 = 0.f, s1 = 0.f;
        for (int c = 0; c < 96; c += 2) { s0 += vy[c]; s1 += vy[c + 1]; }
        float m = (s0 + s1) * (1.f / 96.f);
        s0 = 0.f; s1 = 0.f;
        for (int c = 0; c < 96; c += 2) {
            float d0 = vy[c] - m, d1 = vy[c + 1] - m;
            s0 = fmaf(d0, d0, s0); s1 = fmaf(d1, d1, s1);
        }
        float inv = rsqrtf((s0 + s1) * (1.f / 96.f) + 1e-6f);
        for (int c = 0; c < 96; c++) {
            float v = vy[c];
            vy[c] = v + (v - m) * inv * __ldg(p.ln3g + c) + __ldg(p.ln3b + c);
        }
    }
    __syncthreads();

    // ---- 3. save y row to global (coalesced) ----
    {
        float* gy = g_y + ((size_t)b * 64 + h) * 6144;
        int px = t / 96; int c = t - px * 96;
#pragma unroll
        for (int i = 0; i < 24; i++) {
            gy[t + i * 256] = Zf[px * 97 + c];
            px += 2; c += 64;
            if (c >= 96) { c -= 96; px += 1; }
        }
    }
    __syncthreads();

    // ---- 4. LN1 in place: y -> z ----
    if (t < 64) {
        float* vy = Zf + t * 97;
        float s0 = 0.f, s1 = 0.f;
        for (int c = 0; c < 96; c += 2) { s0 += vy[c]; s1 += vy[c + 1]; }
        float m = (s0 + s1) * (1.f / 96.f);
        s0 = 0.f; s1 = 0.f;
        for (int c = 0; c < 96; c += 2) {
            float d0 = vy[c] - m, d1 = vy[c + 1] - m;
            s0 = fmaf(d0, d0, s0); s1 = fmaf(d1, d1, s1);
        }
        float inv = rsqrtf((s0 + s1) * (1.f / 96.f) + 1e-6f);
        for (int c = 0; c < 96; c++)
            vy[c] = (vy[c] - m) * inv * __ldg(p.ln1g + c) + __ldg(p.ln1b + c);
    }

    // ---- 5. big GEMM over 24 o-chunks ----
    float D[6][4];
#pragma unroll
    for (int j = 0; j < 6; j++)
#pragma unroll
        for (int q = 0; q < 4; q++) D[j][q] = 0.f;

    const float* zrow = Zf + apx * 97;

    for (int o = 0; o < 24; o++) {
        // prefetch w2 chunk into registers
        float wbuf[36];
        {
            const float* wg = p.w2 + o * 96;
            int d_ = dd0, y_ = yy0;
#pragma unroll
            for (int i = 0; i < 36; i++) {
                wbuf[i] = __ldg(wg + d_ * 2304 + y_);
                y_ += 64; d_ += 2;
                if (y_ >= 96) { y_ -= 96; d_ += 1; }
            }
        }
        __syncthreads();   // previous chunk's mma done reading A/W
        int br = o >> 3, j = o & 7;
        if (br == 0) {
            float s0 = __ldg(p.bga + j) * BN_RS;
            float bi = fmaf(s0, __ldg(p.b3a + j), __ldg(p.bba + j));
            agen<3>(AH, AL, zrow, apx, ay0, p.w3a + j * 3, s0, bi);
        } else if (br == 1) {
            float s0 = __ldg(p.bgb + j) * BN_RS;
            float bi = fmaf(s0, __ldg(p.b3b + j), __ldg(p.bbb + j));
            agen<5>(AH, AL, zrow, apx, ay0, p.w3b + j * 5, s0, bi);
        } else {
            float s0 = __ldg(p.bgc + j) * BN_RS;
            float bi = fmaf(s0, __ldg(p.b3c + j), __ldg(p.bbc + j));
            agen<7>(AH, AL, zrow, apx, ay0, p.w3c + j * 7, s0, bi);
        }
        // commit w2 chunk split: W[d][y]
        {
            int d_ = dd0, y_ = yy0;
#pragma unroll
            for (int i = 0; i < 36; i++) {
                float v = wbuf[i];
                __nv_bfloat16 hv = __float2bfloat16(v);
                WH[d_ * ASTRIDE + y_] = hv;
                WL[d_ * ASTRIDE + y_] = __float2bfloat16(v - __bfloat162float(hv));
                y_ += 64; d_ += 2;
                if (y_ >= 96) { y_ -= 96; d_ += 1; }
            }
        }
        __syncthreads();
        mma96(uAH, uAL, uWH, uWL, mt, nbw, lane, D);
    }
    __syncthreads();   // all mma reads of A done -> safe to overwrite as Yr

    // ---- 6. reload y row into Yr (A region) ----
    float* Yr = (float*)(smc + SM_AH);
    {
        const float* gy = g_y + ((size_t)b * 64 + h) * 6144;
        int px = t / 96, c = t - (t / 96) * 96;
#pragma unroll
        for (int i = 0; i < 24; i++) {
            Yr[px * 97 + c] = gy[t + i * 256];
            px += 2; c += 64;
            if (c >= 96) { c -= 96; px += 1; }
        }
    }
    __syncthreads();

    // ---- 7. epilogue: y2 = y + z + gelu(bn2(e+b2)) -> Z ----
    {
        const int r = lane >> 2, q = lane & 3;
        const int m0 = mt * 16 + r;
#pragma unroll
        for (int j = 0; j < 6; j++) {
            int n0 = nbw + j * 8 + 2 * q;
#pragma unroll
            for (int v = 0; v < 4; v++) {
                int m = m0 + ((v >> 1) << 3);
                int d = n0 + (v & 1);
                float s  = __ldg(p.bn2g + d) * BN_RS;
                float bb = __ldg(p.bn2b + d);
                float b2v = __ldg(p.b2 + d);
                float g = gelu_f(fmaf(s, D[j][v] + b2v, bb));
                Zf[m * 97 + d] = Yr[m * 97 + d] + Zf[m * 97 + d] + g;
            }
        }
    }
    __syncthreads();

    // ---- 8. LN2: Z -> ynorm split into AH/AL (overwrites Yr) ----
    if (t < 64) {
        const float* v = Zf + t * 97;
        float s0 = 0.f, s1 = 0.f;
        for (int c = 0; c < 96; c += 2) { s0 += v[c]; s1 += v[c + 1]; }
        float m = (s0 + s1) * (1.f / 96.f);
        s0 = 0.f; s1 = 0.f;
        for (int c = 0; c < 96; c += 2) {
            float d0 = v[c] - m, d1 = v[c + 1] - m;
            s0 = fmaf(d0, d0, s0); s1 = fmaf(d1, d1, s1);
        }
        float inv = rsqrtf((s0 + s1) * (1.f / 96.f) + 1e-6f);
        for (int c = 0; c < 96; c++) {
            float yn = (v[c] - m) * inv * __ldg(p.ln2g + c) + __ldg(p.ln2b + c);
            __nv_bfloat16 hv = __float2bfloat16(yn);
            AH[t * ASTRIDE + c] = hv;
            AL[t * ASTRIDE + c] = __float2bfloat16(yn - __bfloat162float(hv));
        }
    }

    // ---- 9. pin matmul (4 chunks of 96 outputs) -> g_u ----
    for (int oc = 0; oc < 4; oc++) {
        __syncthreads();   // prev copy done with Z; (first iter: LN2 done)
        {
            int oo = dd0, cc = yy0;
#pragma unroll
            for (int i = 0; i < 36; i++) {
                float v = __ldg(p.pinw + (size_t)(oc * 96 + oo) * 96 + cc);
                __nv_bfloat16 hv = __float2bfloat16(v);
                WH[oo * ASTRIDE + cc] = hv;
                WL[oo * ASTRIDE + cc] = __float2bfloat16(v - __bfloat162float(hv));
                cc += 64; oo += 2;
                if (cc >= 96) { cc -= 96; oo += 1; }
            }
        }
        __syncthreads();
        float Du[6][4];
#pragma unroll
        for (int j = 0; j < 6; j++)
#pragma unroll
            for (int q = 0; q < 4; q++) Du[j][q] = 0.f;
        mma96(uAH, uAL, uWH, uWL, mt, nbw, lane, Du);
        // scatter into Z as u[px][o]
        {
            const int r = lane >> 2, q = lane & 3;
            const int m0 = mt * 16 + r;
#pragma unroll
            for (int j = 0; j < 6; j++) {
                int n0 = nbw + j * 8 + 2 * q;
#pragma unroll
                for (int v = 0; v < 4; v++) {
                    int m = m0 + ((v >> 1) << 3);
                    int d = n0 + (v & 1);
                    Zf[m * 97 + d] = Du[j][v] + __ldg(p.pinb + oc * 96 + d);
                }
            }
        }
        __syncthreads();
        // coalesced copy Z -> g_u[b][oc*96+oo][h][px]
        float* ub = g_u + (((size_t)b * 384 + oc * 96) * 64 + h) * 64;
#pragma unroll
        for (int i = 0; i < 24; i++) {
            int e = t + i * 256;
            int oo = e >> 6, px = e & 63;
            ub[(size_t)oo * NHW + px] = Zf[px * 97 + oo];
        }
    }
}

// ---------------------------------------------------------------------------
// Kernel 3: FFN tail (unchanged, verified). g_u -> dwconv(idx-swapped) ->
//           gate -> pout -> out[b][d][w][h] = 2*f
// ---------------------------------------------------------------------------
struct P3 { const float *dww, *dwb, *poutw, *poutb; float* out; };

#define K3_KV   0
#define K3_DWB  3456
#define K3_POB  3840
#define K3_PW   3936
#define K3_HALO 22560
#define K3_G    23360
#define SMEM3_FLOATS 23616
#define SMEM3_BYTES (SMEM3_FLOATS * 4)

__global__ __launch_bounds__(256, 2) void k3_ffn(P3 p) {
    extern __shared__ float sm[];
    const int t = threadIdx.x;
    const int b = blockIdx.x >> 6;
    const int tile = blockIdx.x & 63;
    const int h0 = (tile >> 3) * 8, w0 = (tile & 7) * 8;
    const int tx = t & 31, ty = t >> 5;

    for (int i = t; i < 3456; i += 256) {
        int o = i / 9;
        int rr = i - o * 9;
        int jj = rr / 3, ii = rr - jj * 3;
        sm[K3_KV + i] = __ldg(p.dww + o * 9 + ii * 3 + jj);
    }
    for (int i = t; i < 384; i += 256) sm[K3_DWB + i] = __ldg(p.dwb + i);
    if (t < 96) sm[K3_POB + t] = __ldg(p.poutb + t);
    for (int i = t; i < 18432; i += 256) {
        int d = i / 192;
        int c = i - d * 192;
        sm[K3_PW + c * 97 + d] = __ldg(p.poutw + i);
    }
    __syncthreads();

    const float* ub = g_u + (size_t)b * 384 * NHW;
    unsigned long long acc[12];
#pragma unroll
    for (int i = 0; i < 12; i++) acc[i] = 0ull;

    const int cch = t >> 6;
    const int cpx = t & 63;
    const int chl = cpx >> 3, cwl = cpx & 7;

    for (int c = 0; c < 192; c += 4) {
        __syncthreads();
        for (int e = t; e < 800; e += 256) {
            int tl = e / 100;
            int pos = e - tl * 100;
            int r = pos / 10, cc = pos - r * 10;
            int hh = h0 + r - 1, ww = w0 + cc - 1;
            int ch = c + (tl & 3) + ((tl & 4) ? 192 : 0);
            float v = 0.f;
            if ((unsigned)hh < 64u && (unsigned)ww < 64u)
                v = ub[(size_t)ch * NHW + hh * 64 + ww];
            sm[K3_HALO + tl * 100 + pos] = v;
        }
        __syncthreads();
        {
            const float* ha = sm + K3_HALO + cch * 100;
            const float* hb = sm + K3_HALO + (cch + 4) * 100;
            const float* kva = sm + K3_KV + (c + cch) * 9;
            const float* kvb = sm + K3_KV + (c + cch + 192) * 9;
            float d1 = sm[K3_DWB + c + cch];
            float d2 = sm[K3_DWB + c + cch + 192];
#pragma unroll
            for (int j = 0; j < 3; j++)
#pragma unroll
            for (int i2 = 0; i2 < 3; i2++) {
                    float t1 = ha[(chl + j) * 10 + cwl + i2];
                    float t2 = hb[(chl + j) * 10 + cwl + i2];
                    d1 = fmaf(kva[j * 3 + i2], t1, d1);
                    d2 = fmaf(kvb[j * 3 + i2], t2, d2);
                }
            sm[K3_G + cch * 64 + cpx] = gelu_f(d1) * d2;
        }
        __syncthreads();
#pragma unroll
        for (int cc2 = 0; cc2 < 4; cc2++) {
            const unsigned long long* gp =
                (const unsigned long long*)(sm + K3_G + cc2 * 64 + ty * 8);
            unsigned long long G0 = gp[0], G1 = gp[1], G2 = gp[2], G3 = gp[3];
            const float* wr = sm + K3_PW + (c + cc2) * 97 + tx * 3;
            float w0v = wr[0], w1v = wr[1], w2v = wr[2];
            unsigned long long W0 = pack2(w0v, w0v);
            unsigned long long W1 = pack2(w1v, w1v);
            unsigned long long W2 = pack2(w2v, w2v);
            acc[0]  = fma2(G0, W0, acc[0]);  acc[1]  = fma2(G0, W1, acc[1]);  acc[2]  = fma2(G0, W2, acc[2]);
            acc[3]  = fma2(G1, W0, acc[3]);  acc[4]  = fma2(G1, W1, acc[4]);  acc[5]  = fma2(G1, W2, acc[5]);
            acc[6]  = fma2(G2, W0, acc[6]);  acc[7]  = fma2(G2, W1, acc[7]);  acc[8]  = fma2(G2, W2, acc[8]);
            acc[9]  = fma2(G3, W0, acc[9]);  acc[10] = fma2(G3, W1, acc[10]); acc[11] = fma2(G3, W2, acc[11]);
        }
    }
    __syncthreads();

    float* so = sm + K3_PW;
#pragma unroll
    for (int j = 0; j < 3; j++) {
        int d = tx * 3 + j;
        float bv = sm[K3_POB + d];
#pragma unroll
        for (int pp = 0; pp < 4; pp++) {
            float lo, hi; unpack2(acc[pp * 3 + j], lo, hi);
            so[d * 66 + (2 * pp) * 8 + ty]     = 2.f * (lo + bv);
            so[d * 66 + (2 * pp + 1) * 8 + ty] = 2.f * (hi + bv);
        }
    }
    __syncthreads();

    for (int e = t; e < 768; e += 256) {
        int d = e >> 3, wl = e & 7;
        const float2* s2 = (const float2*)(so + d * 66 + wl * 8);
        float2 v0 = s2[0], v1 = s2[1], v2 = s2[2], v3 = s2[3];
        float2* dst = (float2*)(p.out + (((size_t)b * 96 + d) * 64 + (w0 + wl)) * 64 + h0);
        dst[0] = v0; dst[1] = v1; dst[2] = v2; dst[3] = v3;
    }
}

// ---------------------------------------------------------------------------
// launch
// ---------------------------------------------------------------------------
extern "C" void kernel_launch(void* const* d_in, const int* in_sizes, int n_in,
                              void* d_out, int out_size) {
    (void)in_sizes; (void)n_in; (void)out_size;
    cudaFuncSetAttribute(k2_main, cudaFuncAttributeMaxDynamicSharedMemorySize, SMEM2_BYTES);
    cudaFuncSetAttribute(k3_ffn,  cudaFuncAttributeMaxDynamicSharedMemorySize, SMEM3_BYTES);

    const float* x    = (const float*)d_in[0];
    const float* posw = (const float*)d_in[1];
    const float* posb = (const float*)d_in[2];

    k1_pos<<<NB * NC * NHW / 256, 256>>>(x, posw, posb);

    P2 p2;
    p2.ln1g = (const float*)d_in[3];  p2.ln1b = (const float*)d_in[4];
    p2.ln2g = (const float*)d_in[5];  p2.ln2b = (const float*)d_in[6];
    p2.ln3g = (const float*)d_in[7];  p2.ln3b = (const float*)d_in[8];
    p2.w3a  = (const float*)d_in[9];  p2.b3a  = (const float*)d_in[10];
    p2.bga  = (const float*)d_in[11]; p2.bba  = (const float*)d_in[12];
    p2.w3b  = (const float*)d_in[13]; p2.b3b  = (const float*)d_in[14];
    p2.bgb  = (const float*)d_in[15]; p2.bbb  = (const float*)d_in[16];
    p2.w3c  = (const float*)d_in[17]; p2.b3c  = (const float*)d_in[18];
    p2.bgc  = (const float*)d_in[19]; p2.bbc  = (const float*)d_in[20];
    p2.w2   = (const float*)d_in[21]; p2.b2   = (const float*)d_in[22];
    p2.bn2g = (const float*)d_in[23]; p2.bn2b = (const float*)d_in[24];
    p2.pinw = (const float*)d_in[25]; p2.pinb = (const float*)d_in[26];
    k2_main<<<NB * 64, 256, SMEM2_BYTES>>>(p2);

    P3 p3;
    p3.dww   = (const float*)d_in[27]; p3.dwb   = (const float*)d_in[28];
    p3.poutw = (const float*)d_in[29]; p3.poutb = (const float*)d_in[30];
    p3.out   = (float*)d_out;
    k3_ffn<<<NB * 64, 256, SMEM3_BYTES>>>(p3);
}